// round 13
// baseline (speedup 1.0000x reference)
#include <cuda_runtime.h>
#include <cuda_bf16.h>
#include <math.h>

#define Bsz  4
#define Lsz  2048
#define Dsz  768
#define Hsz  12
#define HDsz 64
#define Msz  (Bsz * Lsz)
#define DD   (Dsz * Dsz)
#define HLsz (Bsz * Hsz * Lsz * HDsz)

typedef __nv_bfloat16 bf16;

// split-bf16 operand storage (no cudaMalloc allowed)
__device__ bf16 g_Qh[HLsz], g_Ql[HLsz];
__device__ bf16 g_Kh[HLsz], g_Kl[HLsz];
__device__ bf16 g_Vh[HLsz], g_Vl[HLsz];
__device__ bf16 g_xh[(size_t)Msz * Dsz], g_xl[(size_t)Msz * Dsz];
__device__ bf16 g_Oh[(size_t)Msz * Dsz], g_Ol[(size_t)Msz * Dsz];
__device__ bf16 g_Wh[4 * DD], g_Wl[4 * DD];   // Wq, Wk, Wv, Wo

// ---------------------------------------------------------------------------
__global__ void split_k(const float* __restrict__ in, bf16* __restrict__ hi,
                        bf16* __restrict__ lo, int n)
{
    int i = (blockIdx.x * blockDim.x + threadIdx.x) * 4;
    if (i >= n) return;
    float4 v = *(const float4*)(in + i);
    bf16 h0 = __float2bfloat16(v.x), h1 = __float2bfloat16(v.y);
    bf16 h2 = __float2bfloat16(v.z), h3 = __float2bfloat16(v.w);
    bf16 l0 = __float2bfloat16(v.x - __bfloat162float(h0));
    bf16 l1 = __float2bfloat16(v.y - __bfloat162float(h1));
    bf16 l2 = __float2bfloat16(v.z - __bfloat162float(h2));
    bf16 l3 = __float2bfloat16(v.w - __bfloat162float(h3));
    ((__nv_bfloat162*)(hi + i))[0] = __halves2bfloat162(h0, h1);
    ((__nv_bfloat162*)(hi + i))[1] = __halves2bfloat162(h2, h3);
    ((__nv_bfloat162*)(lo + i))[0] = __halves2bfloat162(l0, l1);
    ((__nv_bfloat162*)(lo + i))[1] = __halves2bfloat162(l2, l3);
}

// ---------------------------------------------------------------------------
__device__ __forceinline__ void mma_bf16(float* c, const unsigned* a,
                                         const unsigned* b)
{
    asm volatile(
        "mma.sync.aligned.m16n8k16.row.col.f32.bf16.bf16.f32 "
        "{%0,%1,%2,%3}, {%4,%5,%6,%7}, {%8,%9}, {%0,%1,%2,%3};\n"
        : "+f"(c[0]), "+f"(c[1]), "+f"(c[2]), "+f"(c[3])
        : "r"(a[0]), "r"(a[1]), "r"(a[2]), "r"(a[3]),
          "r"(b[0]), "r"(b[1]));
}

__device__ __forceinline__ void ldsm_x4(unsigned* r, const void* p)
{
    unsigned a = (unsigned)__cvta_generic_to_shared(p);
    asm volatile("ldmatrix.sync.aligned.m8n8.x4.shared.b16 {%0,%1,%2,%3}, [%4];"
                 : "=r"(r[0]), "=r"(r[1]), "=r"(r[2]), "=r"(r[3]) : "r"(a));
}

__device__ __forceinline__ void ldsm_x4_t(unsigned* r, const void* p)
{
    unsigned a = (unsigned)__cvta_generic_to_shared(p);
    asm volatile("ldmatrix.sync.aligned.m8n8.x4.trans.shared.b16 {%0,%1,%2,%3}, [%4];"
                 : "=r"(r[0]), "=r"(r[1]), "=r"(r[2]), "=r"(r[3]) : "r"(a));
}

__device__ __forceinline__ unsigned pack2(float a, float b)
{
    __nv_bfloat162 t = __floats2bfloat162_rn(a, b);   // a in low half
    return *(unsigned*)&t;
}

// ---------------------------------------------------------------------------
// Split-bf16 GEMM: C = Ah*Wh + Ah*Wl + Al*Wh, fp32 accum.
// MODE 0: fp32 row-major out.
// MODE 1: head-split SPLIT-bf16 out (hi/lo pairs), scaled by sc (Q: 0.125).
// ---------------------------------------------------------------------------
template <int MODE>
__global__ void __launch_bounds__(256, 2) mma_gemm_k(
    const bf16* __restrict__ Ah, const bf16* __restrict__ Al,
    const bf16* __restrict__ Whb, const bf16* __restrict__ Wlb,
    const float* b0p, const float* b1p, const float* b2p,
    float* fo,
    bf16* ph0, bf16* pl0, bf16* ph1, bf16* pl1, bf16* ph2, bf16* pl2)
{
    __shared__ bf16 sAh[128][40], sAl[128][40];
    __shared__ unsigned sBh[16][136], sBl[16][136];

    const int z = blockIdx.z;
    const bf16* Wh = Whb + (size_t)z * DD;
    const bf16* Wl = Wlb + (size_t)z * DD;
    const float* bias = (z == 0) ? b0p : (z == 1) ? b1p : b2p;
    bf16* outh = (z == 0) ? ph0 : (z == 1) ? ph1 : ph2;
    bf16* outl = (z == 0) ? pl0 : (z == 1) ? pl1 : pl2;
    const float sc = (MODE == 1 && z == 0) ? 0.125f : 1.f;

    const int tid  = threadIdx.x;
    const int lane = tid & 31;
    const int wid  = tid >> 5;
    const int wm   = wid & 3;
    const int wn   = wid >> 2;
    const int m0   = blockIdx.y * 128;
    const int n0   = blockIdx.x * 128;
    const int lr   = lane >> 2;
    const int kq   = (lane & 3) * 2;

    float acc[2][8][4];
#pragma unroll
    for (int mt = 0; mt < 2; mt++)
#pragma unroll
        for (int nt = 0; nt < 8; nt++)
#pragma unroll
            for (int j = 0; j < 4; j++) acc[mt][nt][j] = 0.f;

    for (int k0 = 0; k0 < Dsz; k0 += 32) {
        __syncthreads();
#pragma unroll
        for (int i = 0; i < 2; i++) {
            int f  = tid + i * 256;
            int m  = f >> 2;
            int k8 = (f & 3) << 3;
            *(uint4*)&sAh[m][k8] =
                *(const uint4*)(Ah + (size_t)(m0 + m) * Dsz + k0 + k8);
            *(uint4*)&sAl[m][k8] =
                *(const uint4*)(Al + (size_t)(m0 + m) * Dsz + k0 + k8);
        }
        {
            int kp  = tid >> 4;
            int n8o = (tid & 15) * 8;
            const bf16* src0 = Wh + (size_t)(k0 + 2 * kp) * Dsz + n0 + n8o;
            uint4 uh = *(const uint4*)src0;
            uint4 vh = *(const uint4*)(src0 + Dsz);
            const bf16* src1 = Wl + (size_t)(k0 + 2 * kp) * Dsz + n0 + n8o;
            uint4 ul = *(const uint4*)src1;
            uint4 vl = *(const uint4*)(src1 + Dsz);
            unsigned wh[8], wl[8];
            const unsigned short* uhs = (const unsigned short*)&uh;
            const unsigned short* vhs = (const unsigned short*)&vh;
            const unsigned short* uls = (const unsigned short*)&ul;
            const unsigned short* vls = (const unsigned short*)&vl;
#pragma unroll
            for (int j = 0; j < 8; j++) {
                wh[j] = (unsigned)uhs[j] | ((unsigned)vhs[j] << 16);
                wl[j] = (unsigned)uls[j] | ((unsigned)vls[j] << 16);
            }
            *(uint4*)&sBh[kp][n8o]     = *(uint4*)&wh[0];
            *(uint4*)&sBh[kp][n8o + 4] = *(uint4*)&wh[4];
            *(uint4*)&sBl[kp][n8o]     = *(uint4*)&wl[0];
            *(uint4*)&sBl[kp][n8o + 4] = *(uint4*)&wl[4];
        }
        __syncthreads();

#pragma unroll
        for (int s = 0; s < 2; s++) {
            const int ks = s * 16;
            unsigned ah[2][4], al[2][4];
#pragma unroll
            for (int mt = 0; mt < 2; mt++) {
                int mb = wm * 32 + mt * 16;
                ah[mt][0] = *(const unsigned*)&sAh[mb + lr][ks + kq];
                ah[mt][1] = *(const unsigned*)&sAh[mb + lr + 8][ks + kq];
                ah[mt][2] = *(const unsigned*)&sAh[mb + lr][ks + kq + 8];
                ah[mt][3] = *(const unsigned*)&sAh[mb + lr + 8][ks + kq + 8];
                al[mt][0] = *(const unsigned*)&sAl[mb + lr][ks + kq];
                al[mt][1] = *(const unsigned*)&sAl[mb + lr + 8][ks + kq];
                al[mt][2] = *(const unsigned*)&sAl[mb + lr][ks + kq + 8];
                al[mt][3] = *(const unsigned*)&sAl[mb + lr + 8][ks + kq + 8];
            }
            const int kb = s * 8 + (lane & 3);
#pragma unroll
            for (int nt = 0; nt < 8; nt++) {
                int nn = wn * 64 + nt * 8 + lr;
                unsigned bh[2], bl[2];
                bh[0] = sBh[kb][nn];     bh[1] = sBh[kb + 4][nn];
                bl[0] = sBl[kb][nn];     bl[1] = sBl[kb + 4][nn];
#pragma unroll
                for (int mt = 0; mt < 2; mt++) {
                    mma_bf16(acc[mt][nt], ah[mt], bh);
                    mma_bf16(acc[mt][nt], ah[mt], bl);
                    mma_bf16(acc[mt][nt], al[mt], bh);
                }
            }
        }
    }

#pragma unroll
    for (int mt = 0; mt < 2; mt++) {
#pragma unroll
        for (int nt = 0; nt < 8; nt++) {
            int m = m0 + wm * 32 + mt * 16 + lr;
            int n = n0 + wn * 64 + nt * 8 + kq;
            float bv0 = bias[n], bv1 = bias[n + 1];
            float v0 = (acc[mt][nt][0] + bv0) * sc;
            float v1 = (acc[mt][nt][1] + bv1) * sc;
            float v2 = (acc[mt][nt][2] + bv0) * sc;
            float v3 = (acc[mt][nt][3] + bv1) * sc;
            if (MODE == 0) {
                *(float2*)(fo + (size_t)m * Dsz + n) = make_float2(v0, v1);
                *(float2*)(fo + (size_t)(m + 8) * Dsz + n) = make_float2(v2, v3);
            } else {
                int b = m >> 11, l = m & (Lsz - 1);
                int h = n >> 6,  d = n & 63;
                size_t base = ((size_t)(b * Hsz + h) * Lsz + l) * HDsz + d;
                bf16 h0 = __float2bfloat16(v0), h1 = __float2bfloat16(v1);
                bf16 h2 = __float2bfloat16(v2), h3 = __float2bfloat16(v3);
                *(unsigned*)(outh + base) = pack2(v0, v1);
                *(unsigned*)(outh + base + 8 * HDsz) = pack2(v2, v3);
                *(unsigned*)(outl + base) =
                    pack2(v0 - __bfloat162float(h0), v1 - __bfloat162float(h1));
                *(unsigned*)(outl + base + 8 * HDsz) =
                    pack2(v2 - __bfloat162float(h2), v3 - __bfloat162float(h3));
            }
        }
    }
}

// ---------------------------------------------------------------------------
// Tensor-core flash attention, split-bf16. Q/K/V arrive PRE-SPLIT (and Q
// pre-scaled) from the projection epilogue — tile loads are pure copies.
// ---------------------------------------------------------------------------
__global__ void __launch_bounds__(128) attn_mma_k()
{
    __shared__ bf16 sKh[64][72], sKl[64][72];   // also used to stage Q
    __shared__ bf16 sVh[64][72], sVl[64][72];

    const int bh   = blockIdx.y;
    const int qt   = blockIdx.x;
    const int tid  = threadIdx.x;
    const int lane = tid & 31;
    const int wid  = tid >> 5;
    const int band = wid * 16;
    const int lr   = lane >> 2;
    const int lc2  = (lane & 3) * 2;

    const size_t hb = (size_t)bh * Lsz * HDsz;
    const bf16* Qhg = g_Qh + hb + (size_t)qt * 64 * HDsz;
    const bf16* Qlg = g_Ql + hb + (size_t)qt * 64 * HDsz;

    // --- stage pre-split Q ---
#pragma unroll
    for (int i = 0; i < 8; i++) {
        int f  = tid + i * 128;
        int r  = f >> 4;
        int d4 = (f & 15) << 2;
        *(uint2*)&sKh[r][d4] = *(const uint2*)(Qhg + r * HDsz + d4);
        *(uint2*)&sKl[r][d4] = *(const uint2*)(Qlg + r * HDsz + d4);
    }
    __syncthreads();

    unsigned qh[4][4], ql[4][4];
#pragma unroll
    for (int ks = 0; ks < 4; ks++) {
        int row = band + (lane & 15);
        int col = ks * 16 + (lane >> 4) * 8;
        ldsm_x4(qh[ks], &sKh[row][col]);
        ldsm_x4(ql[ks], &sKl[row][col]);
    }

    float accO[8][4];
#pragma unroll
    for (int nt = 0; nt < 8; nt++)
#pragma unroll
        for (int j = 0; j < 4; j++) accO[nt][j] = 0.f;
    float m0 = -INFINITY, m1 = -INFINITY, l0 = 0.f, l1 = 0.f;

    for (int kt = 0; kt < Lsz / 64; kt++) {
        __syncthreads();
        // --- copy pre-split K,V tiles (no conversion) ---
        const size_t tb = hb + (size_t)kt * 64 * HDsz;
#pragma unroll
        for (int i = 0; i < 8; i++) {
            int f  = tid + i * 128;
            int r  = f >> 4;
            int d4 = (f & 15) << 2;
            size_t off = tb + r * HDsz + d4;
            *(uint2*)&sKh[r][d4] = *(const uint2*)(g_Kh + off);
            *(uint2*)&sKl[r][d4] = *(const uint2*)(g_Kl + off);
            *(uint2*)&sVh[r][d4] = *(const uint2*)(g_Vh + off);
            *(uint2*)&sVl[r][d4] = *(const uint2*)(g_Vl + off);
        }
        __syncthreads();

        // --- S = Q K^T ---
        float s[8][4];
#pragma unroll
        for (int nt = 0; nt < 8; nt++)
#pragma unroll
            for (int j = 0; j < 4; j++) s[nt][j] = 0.f;

#pragma unroll
        for (int kp = 0; kp < 2; kp++) {
#pragma unroll
            for (int nt = 0; nt < 8; nt++) {
                int key = nt * 8 + (lane & 7);
                int col = kp * 32 + (lane >> 3) * 8;
                unsigned bh4[4], bl4[4];
                ldsm_x4(bh4, &sKh[key][col]);
                ldsm_x4(bl4, &sKl[key][col]);
                mma_bf16(s[nt], qh[2 * kp],     &bh4[0]);
                mma_bf16(s[nt], qh[2 * kp],     &bl4[0]);
                mma_bf16(s[nt], ql[2 * kp],     &bh4[0]);
                mma_bf16(s[nt], qh[2 * kp + 1], &bh4[2]);
                mma_bf16(s[nt], qh[2 * kp + 1], &bl4[2]);
                mma_bf16(s[nt], ql[2 * kp + 1], &bh4[2]);
            }
        }

        // --- online softmax ---
        float mx0 = -INFINITY, mx1 = -INFINITY;
#pragma unroll
        for (int nt = 0; nt < 8; nt++) {
            mx0 = fmaxf(mx0, fmaxf(s[nt][0], s[nt][1]));
            mx1 = fmaxf(mx1, fmaxf(s[nt][2], s[nt][3]));
        }
        mx0 = fmaxf(mx0, __shfl_xor_sync(0xffffffffu, mx0, 1));
        mx0 = fmaxf(mx0, __shfl_xor_sync(0xffffffffu, mx0, 2));
        mx1 = fmaxf(mx1, __shfl_xor_sync(0xffffffffu, mx1, 1));
        mx1 = fmaxf(mx1, __shfl_xor_sync(0xffffffffu, mx1, 2));
        float mn0 = fmaxf(m0, mx0), mn1 = fmaxf(m1, mx1);
        float a0 = __expf(m0 - mn0), a1 = __expf(m1 - mn1);
        float sum0 = 0.f, sum1 = 0.f;
#pragma unroll
        for (int nt = 0; nt < 8; nt++) {
            s[nt][0] = __expf(s[nt][0] - mn0);
            s[nt][1] = __expf(s[nt][1] - mn0);
            s[nt][2] = __expf(s[nt][2] - mn1);
            s[nt][3] = __expf(s[nt][3] - mn1);
            sum0 += s[nt][0] + s[nt][1];
            sum1 += s[nt][2] + s[nt][3];
        }
        sum0 += __shfl_xor_sync(0xffffffffu, sum0, 1);
        sum0 += __shfl_xor_sync(0xffffffffu, sum0, 2);
        sum1 += __shfl_xor_sync(0xffffffffu, sum1, 1);
        sum1 += __shfl_xor_sync(0xffffffffu, sum1, 2);
        l0 = l0 * a0 + sum0;  m0 = mn0;
        l1 = l1 * a1 + sum1;  m1 = mn1;
#pragma unroll
        for (int nt = 0; nt < 8; nt++) {
            accO[nt][0] *= a0;  accO[nt][1] *= a0;
            accO[nt][2] *= a1;  accO[nt][3] *= a1;
        }

        // --- O += P V ---
#pragma unroll
        for (int ks = 0; ks < 4; ks++) {
            unsigned ph[4], pl[4];
            {
                float p00 = s[2*ks][0],   p01 = s[2*ks][1];
                float p02 = s[2*ks][2],   p03 = s[2*ks][3];
                float p10 = s[2*ks+1][0], p11 = s[2*ks+1][1];
                float p12 = s[2*ks+1][2], p13 = s[2*ks+1][3];
                ph[0] = pack2(p00, p01);  ph[1] = pack2(p02, p03);
                ph[2] = pack2(p10, p11);  ph[3] = pack2(p12, p13);
                bf16 h;
                h = __float2bfloat16(p00); float r00 = p00 - __bfloat162float(h);
                h = __float2bfloat16(p01); float r01 = p01 - __bfloat162float(h);
                h = __float2bfloat16(p02); float r02 = p02 - __bfloat162float(h);
                h = __float2bfloat16(p03); float r03 = p03 - __bfloat162float(h);
                h = __float2bfloat16(p10); float r10 = p10 - __bfloat162float(h);
                h = __float2bfloat16(p11); float r11 = p11 - __bfloat162float(h);
                h = __float2bfloat16(p12); float r12 = p12 - __bfloat162float(h);
                h = __float2bfloat16(p13); float r13 = p13 - __bfloat162float(h);
                pl[0] = pack2(r00, r01);  pl[1] = pack2(r02, r03);
                pl[2] = pack2(r10, r11);  pl[3] = pack2(r12, r13);
            }
#pragma unroll
            for (int np = 0; np < 4; np++) {
                int row = ks * 16 + (lane & 15);
                int col = np * 16 + (lane >> 4) * 8;
                unsigned vh4[4], vl4[4];
                ldsm_x4_t(vh4, &sVh[row][col]);
                ldsm_x4_t(vl4, &sVl[row][col]);
                mma_bf16(accO[2 * np],     ph, &vh4[0]);
                mma_bf16(accO[2 * np],     ph, &vl4[0]);
                mma_bf16(accO[2 * np],     pl, &vh4[0]);
                mma_bf16(accO[2 * np + 1], ph, &vh4[2]);
                mma_bf16(accO[2 * np + 1], ph, &vl4[2]);
                mma_bf16(accO[2 * np + 1], pl, &vh4[2]);
            }
        }
    }

    // --- epilogue: normalize, split, write to out-proj A operand ---
    const float inv0 = 1.f / l0, inv1 = 1.f / l1;
    const int b = bh / Hsz, h = bh % Hsz;
    const int q0 = qt * 64 + band + lr;
#pragma unroll
    for (int nt = 0; nt < 8; nt++) {
        int d = nt * 8 + lc2;
        size_t base0 = ((size_t)(b * Lsz + q0)) * Dsz + h * HDsz + d;
        size_t base1 = ((size_t)(b * Lsz + q0 + 8)) * Dsz + h * HDsz + d;
        float o0 = accO[nt][0] * inv0, o1 = accO[nt][1] * inv0;
        float o2 = accO[nt][2] * inv1, o3 = accO[nt][3] * inv1;
        bf16 h0 = __float2bfloat16(o0), h1 = __float2bfloat16(o1);
        bf16 h2 = __float2bfloat16(o2), h3 = __float2bfloat16(o3);
        *(unsigned*)(g_Oh + base0) = pack2(o0, o1);
        *(unsigned*)(g_Oh + base1) = pack2(o2, o3);
        *(unsigned*)(g_Ol + base0) =
            pack2(o0 - __bfloat162float(h0), o1 - __bfloat162float(h1));
        *(unsigned*)(g_Ol + base1) =
            pack2(o2 - __bfloat162float(h2), o3 - __bfloat162float(h3));
    }
}

// ---------------------------------------------------------------------------
extern "C" void kernel_launch(void* const* d_in, const int* in_sizes, int n_in,
                              void* d_out, int out_size)
{
    const float* x  = (const float*)d_in[0];
    const float* Wq = (const float*)d_in[1];
    const float* bq = (const float*)d_in[2];
    const float* Wk = (const float*)d_in[3];
    const float* bk = (const float*)d_in[4];
    const float* Wv = (const float*)d_in[5];
    const float* bv = (const float*)d_in[6];
    const float* Wo = (const float*)d_in[7];
    const float* bo = (const float*)d_in[8];
    float* out = (float*)d_out;

    bf16 *qh, *ql, *kh, *kl, *vh, *vl, *xh, *xl, *oh, *ol, *wh, *wl;
    cudaGetSymbolAddress((void**)&qh, g_Qh);
    cudaGetSymbolAddress((void**)&ql, g_Ql);
    cudaGetSymbolAddress((void**)&kh, g_Kh);
    cudaGetSymbolAddress((void**)&kl, g_Kl);
    cudaGetSymbolAddress((void**)&vh, g_Vh);
    cudaGetSymbolAddress((void**)&vl, g_Vl);
    cudaGetSymbolAddress((void**)&xh, g_xh);
    cudaGetSymbolAddress((void**)&xl, g_xl);
    cudaGetSymbolAddress((void**)&oh, g_Oh);
    cudaGetSymbolAddress((void**)&ol, g_Ol);
    cudaGetSymbolAddress((void**)&wh, g_Wh);
    cudaGetSymbolAddress((void**)&wl, g_Wl);

    const int nX = Msz * Dsz;
    split_k<<<(nX / 4 + 255) / 256, 256>>>(x, xh, xl, nX);
    split_k<<<(DD / 4 + 255) / 256, 256>>>(Wq, wh + 0 * DD, wl + 0 * DD, DD);
    split_k<<<(DD / 4 + 255) / 256, 256>>>(Wk, wh + 1 * DD, wl + 1 * DD, DD);
    split_k<<<(DD / 4 + 255) / 256, 256>>>(Wv, wh + 2 * DD, wl + 2 * DD, DD);
    split_k<<<(DD / 4 + 255) / 256, 256>>>(Wo, wh + 3 * DD, wl + 3 * DD, DD);

    // QKV projections -> split-bf16 head-split operands (Q pre-scaled)
    mma_gemm_k<1><<<dim3(Dsz / 128, Msz / 128, 3), 256>>>(
        xh, xl, wh, wl, bq, bk, bv,
        nullptr, qh, ql, kh, kl, vh, vl);

    attn_mma_k<<<dim3(Lsz / 64, Bsz * Hsz), 128>>>();

    mma_gemm_k<0><<<dim3(Dsz / 128, Msz / 128, 1), 256>>>(
        oh, ol, wh + 3 * DD, wl + 3 * DD, bo, bo, bo,
        out, nullptr, nullptr, nullptr, nullptr, nullptr, nullptr);
}